// round 9
// baseline (speedup 1.0000x reference)
#include <cuda_runtime.h>
#include <cstdint>

#define B_   64
#define T_   512
#define D_   256
#define H_   256
#define G4_  1024
#define M_   (B_ * T_)   // 32768

// ---------------- scratch (device globals; no allocations allowed) ----------
__device__ float g_xg[(size_t)M_ * G4_];      // [B][T][4H] gate preacts
__device__ float g_y1[(size_t)B_ * T_ * H_];  // layer-1 output
__device__ float g_masks[6][B_ * H_];         // [layer*3 + {out,h,c}][B*H]

// ---------------- packed fp32x2 helpers -------------------------------------
#define FMA2(acc, a, b) \
  asm("fma.rn.f32x2 %0, %1, %2, %0;" : "+l"(acc) : "l"(a), "l"(b))
#define ADD2(d, a, b) \
  asm("add.rn.f32x2 %0, %1, %2;" : "=l"(d) : "l"(a), "l"(b))
#define PACKD(d, s) \
  asm("mov.b64 %0, {%1, %1};" : "=l"(d) : "f"(s))
#define PACK2V(d, lo, hi) \
  asm("mov.b64 %0, {%1, %2};" : "=l"(d) : "f"(lo), "f"(hi))
#define UNPACK2(lo, hi, s) \
  asm("mov.b64 {%0, %1}, %2;" : "=f"(lo), "=f"(hi) : "l"(s))

__device__ __forceinline__ float fast_sigmoid(float x) {
  return __fdividef(1.f, 1.f + __expf(-x));
}
__device__ __forceinline__ float fast_tanh(float x) {
  float a = fabsf(x);
  float e = __expf(-2.f * a);
  float t = __fdividef(1.f - e, 1.f + e);
  return copysignf(t, x);
}

// ---------------- mbarrier helpers -------------------------------------------
#define MBAR_INIT(addr, cnt) \
  asm volatile("mbarrier.init.shared.b64 [%0], %1;" :: "r"(addr), "r"(cnt) : "memory")

#define MBAR_EXPECT(addr, bytes) \
  asm volatile("mbarrier.arrive.expect_tx.shared.b64 _, [%0], %1;" \
               :: "r"(addr), "r"(bytes) : "memory")

#define WAIT_MBAR(addr, par) do {                                              \
  uint32_t _done;                                                              \
  asm volatile("{\n\t.reg .pred p;\n\t"                                        \
    "mbarrier.try_wait.parity.acquire.cluster.shared::cta.b64 p, [%1], %2;\n\t"\
    "selp.b32 %0, 1, 0, p;\n\t}" : "=r"(_done) : "r"(addr), "r"(par) : "memory"); \
  while (!_done) {                                                             \
    asm volatile("{\n\t.reg .pred p;\n\t"                                      \
      "mbarrier.try_wait.parity.acquire.cluster.shared::cta.b64 p, [%1], %2, 0x989680;\n\t" \
      "selp.b32 %0, 1, 0, p;\n\t}" : "=r"(_done) : "r"(addr), "r"(par) : "memory"); \
  }                                                                            \
} while (0)

__device__ __forceinline__ uint32_t mapa_smem(uint32_t laddr, uint32_t rank) {
  uint32_t ra;
  asm("mapa.shared::cluster.u32 %0, %1, %2;" : "=r"(ra) : "r"(laddr), "r"(rank));
  return ra;
}

// ---------------- threefry2x32 (exact JAX implementation) -------------------
__device__ __forceinline__ void threefry2x32(uint32_t k0, uint32_t k1,
                                             uint32_t x0, uint32_t x1,
                                             uint32_t& o0, uint32_t& o1) {
  uint32_t ks2 = k0 ^ k1 ^ 0x1BD11BDAu;
#define TF_R(rot) { x0 += x1; x1 = (x1 << (rot)) | (x1 >> (32 - (rot))); x1 ^= x0; }
  x0 += k0; x1 += k1;
  TF_R(13) TF_R(15) TF_R(26) TF_R(6)
  x0 += k1;  x1 += ks2 + 1u;
  TF_R(17) TF_R(29) TF_R(16) TF_R(24)
  x0 += ks2; x1 += k0 + 2u;
  TF_R(13) TF_R(15) TF_R(26) TF_R(6)
  x0 += k0;  x1 += k1 + 3u;
  TF_R(17) TF_R(29) TF_R(16) TF_R(24)
  x0 += k1;  x1 += ks2 + 4u;
  TF_R(13) TF_R(15) TF_R(26) TF_R(6)
  x0 += ks2; x1 += k0 + 5u;
#undef TF_R
  o0 = x0; o1 = x1;
}

__device__ __forceinline__ float mask_val(uint32_t bits) {
  float u = __uint_as_float(0x3f800000u | (bits >> 9)) - 1.0f;
  return (u < 0.75f) ? (1.0f / 0.75f) : 0.0f;
}

__global__ void mask_kernel() {
  int mid   = blockIdx.y;
  int layer = mid / 3, which = mid % 3;
  int e = blockIdx.x * blockDim.x + threadIdx.x;   // 0..16383

  uint32_t Lk0, Lk1, mk0, mk1, b1, b2;
  threefry2x32(0u, 42u, 0u, (uint32_t)layer, Lk0, Lk1);
  threefry2x32(Lk0, Lk1, 0u, (uint32_t)which, mk0, mk1);
  threefry2x32(mk0, mk1, 0u, (uint32_t)e, b1, b2);
  g_masks[mid][e] = mask_val(b1 ^ b2);
}

// ---------------- input-projection GEMM: Y[m][n] = X[m,:]·W[n,:] + bias -----
__global__ void __launch_bounds__(256, 2) gemm_xg_kernel(
    const float* __restrict__ X, const float* __restrict__ W,
    const float* __restrict__ bi, const float* __restrict__ bh,
    float* __restrict__ Y) {
  const int K = 256, N = 1024;
  __shared__ float As[32][132];
  __shared__ float Bs[32][132];
  int bm = blockIdx.y * 128, bn = blockIdx.x * 128;
  int tid = threadIdx.x;
  int tx = tid & 15, ty = tid >> 4;

  uint64_t acc[8][4];
#pragma unroll
  for (int i = 0; i < 8; i++)
#pragma unroll
    for (int j = 0; j < 4; j++) acc[i][j] = 0ull;

  for (int k0 = 0; k0 < K; k0 += 32) {
#pragma unroll
    for (int i = 0; i < 4; i++) {
      int idx = tid + i * 256;
      int row = idx >> 3;
      int kk  = (idx & 7) << 2;
      float4 va = *(const float4*)&X[(size_t)(bm + row) * K + k0 + kk];
      As[kk + 0][row] = va.x; As[kk + 1][row] = va.y;
      As[kk + 2][row] = va.z; As[kk + 3][row] = va.w;
      float4 vb = *(const float4*)&W[(size_t)(bn + row) * K + k0 + kk];
      Bs[kk + 0][row] = vb.x; Bs[kk + 1][row] = vb.y;
      Bs[kk + 2][row] = vb.z; Bs[kk + 3][row] = vb.w;
    }
    __syncthreads();
#pragma unroll
    for (int kk = 0; kk < 32; kk++) {
      float4 a0 = *(const float4*)&As[kk][ty * 8];
      float4 a1 = *(const float4*)&As[kk][ty * 8 + 4];
      ulonglong2 b0 = *(const ulonglong2*)&Bs[kk][tx * 8];
      ulonglong2 b1 = *(const ulonglong2*)&Bs[kk][tx * 8 + 4];
      float av[8] = {a0.x, a0.y, a0.z, a0.w, a1.x, a1.y, a1.z, a1.w};
#pragma unroll
      for (int i = 0; i < 8; i++) {
        uint64_t ap;
        PACKD(ap, av[i]);
        FMA2(acc[i][0], ap, b0.x);
        FMA2(acc[i][1], ap, b0.y);
        FMA2(acc[i][2], ap, b1.x);
        FMA2(acc[i][3], ap, b1.y);
      }
    }
    __syncthreads();
  }

  float bias[8];
#pragma unroll
  for (int j = 0; j < 8; j++) {
    int n = bn + tx * 8 + j;
    bias[j] = bi[n] + bh[n];
  }
#pragma unroll
  for (int i = 0; i < 8; i++) {
    float c[8];
#pragma unroll
    for (int j = 0; j < 4; j++) UNPACK2(c[2 * j], c[2 * j + 1], acc[i][j]);
    size_t base = (size_t)(bm + ty * 8 + i) * N + bn + tx * 8;
    float4 v0 = make_float4(c[0] + bias[0], c[1] + bias[1],
                            c[2] + bias[2], c[3] + bias[3]);
    float4 v1 = make_float4(c[4] + bias[4], c[5] + bias[5],
                            c[6] + bias[6], c[7] + bias[7]);
    *(float4*)&Y[base]     = v0;
    *(float4*)&Y[base + 4] = v1;
  }
}

// ---------------- persistent recurrent LSTM layer ---------------------------
// As R8 (16 clusters x 8 CTAs, 2 pipelined batch-groups, warp-autonomous
// steps, st.async h broadcast), but h is stored PRE-DUPLICATED:
//   hbuf[k] = {h_b0, h_b0, h_b1, h_b1}  (16 B per k)
// so the matmul inner loop is 1 LDS.128 + 2 FFMA2 per k (no PACKD).
// Layout: q-block (32 k) stride 528 B (16 B pad) -> conflict-free LDS.128.
#define HB_BUF_B   4224                        // 8 q-blocks * 528
#define HB_G_B     (2 * HB_BUF_B)              // per group (2 parities)
#define SCR_OFF    (4 * HB_BUF_B)              // 16896
#define SCR_W_B    96                          // 64B exch + 32B hstage
#define MB_OFF     (SCR_OFF + 16 * SCR_W_B)    // 18432
#define SMEM_TOT   (MB_OFF + 32)

__global__ void __launch_bounds__(512, 1) __cluster_dims__(8, 1, 1)
lstm_layer_kernel(const float* __restrict__ xg, const float* __restrict__ Whh,
                  const float* __restrict__ mask_out,
                  const float* __restrict__ mask_h,
                  const float* __restrict__ mask_c,
                  float* __restrict__ out) {
  __shared__ __align__(16) unsigned char sm[SMEM_TOT];
  uint32_t sb = (uint32_t)__cvta_generic_to_shared(sm);

  int tid  = threadIdx.x;
  int w    = tid >> 5;
  int lane = tid & 31;
  uint32_t s;
  asm("mov.u32 %0, %%cluster_ctarank;" : "=r"(s));
  int cb = blockIdx.x >> 3;             // cluster id (batches cb*4 .. cb*4+3)

  int gate = lane & 3;
  int q    = lane >> 2;                 // 32-k slice 0..7

  // ---- weights: rows (gate, units 2w/2w+1), k in [32q, 32q+32) -------------
  uint64_t wp[32];
  {
    int R0 = gate * 256 + (int)s * 32 + 2 * w;
    const float* w0 = Whh + (size_t)R0 * 256 + q * 32;
    const float* w1 = w0 + 256;
#pragma unroll
    for (int kk = 0; kk < 32; kk++) PACK2V(wp[kk], w0[kk], w1[kk]);
  }

  // ---- zero h buffers, init mbarriers --------------------------------------
  for (int idx = tid; idx < SCR_OFF / 4; idx += 512)
    ((float*)sm)[idx] = 0.f;
  if (tid == 0) {
#pragma unroll
    for (int i = 0; i < 4; i++) MBAR_INIT(sb + MB_OFF + i * 8, 1);
  }

  // ---- finalize-role (lane<4): (u = lane>>1, b = lane&1), both groups ------
  int u = lane >> 1, b = lane & 1;
  int gu = (int)s * 32 + 2 * w + u;
  float cst[2] = {0.f, 0.f};
  float mo[2], mhv[2], mcv[2];
  size_t out_b[2];
  const float* xg_b[2];
  if (lane < 4) {
#pragma unroll
    for (int g = 0; g < 2; g++) {
      int bb = cb * 4 + g * 2 + b;
      mo[g]  = mask_out[bb * 256 + gu];
      mhv[g] = mask_h  [bb * 256 + gu];
      mcv[g] = mask_c  [bb * 256 + gu];
      out_b[g] = (size_t)bb * (T_ * H_) + gu;
      xg_b[g]  = xg + (size_t)bb * (T_ * G4_) + gu;
    }
  }

  // ---- store-role (all 32 lanes): rank = lane>>2, su=(lane>>1)&1,
  //      piece = lane&1 (b-pair).  8 B duplicated value per task. ------------
  uint32_t r_hb[2], r_mb[2];
  uint32_t src_hst = sb + SCR_OFF + w * SCR_W_B + 64 + (lane & 3) * 8;
  {
    uint32_t rk = (uint32_t)(lane >> 2) & 7;
    // dest float16B slot: global k = s*32 + 2w + su; offset = s*528 + (2w+su)*16
    // + piece*8 = s*528 + w*32 + (lane&3)*8
    uint32_t dest_off = (uint32_t)((int)s * 528 + w * 32 + (lane & 3) * 8);
#pragma unroll
    for (int g = 0; g < 2; g++) {
      r_hb[g] = mapa_smem(sb + g * HB_G_B + dest_off, rk);
      r_mb[g] = mapa_smem(sb + MB_OFF + g * 16, rk);
    }
  }

  float*    scr   = (float*)(sm + SCR_OFF + w * SCR_W_B);
  uint64_t* sx    = (uint64_t*)scr;

  __syncthreads();
  asm volatile("barrier.cluster.arrive.aligned;" ::: "memory");
  asm volatile("barrier.cluster.wait.aligned;"   ::: "memory");

  for (int t = 0; t < T_; t++) {
    int buf  = t & 1;
    int nbuf = buf ^ 1;
    uint32_t wpar = (uint32_t)(((t - 1) >> 1) & 1);

    // post expected bytes for the buffers written this step (4096 B each)
    if (tid == 0) {
      MBAR_EXPECT(sb + MB_OFF + 0 * 16 + nbuf * 8, 4096u);
      MBAR_EXPECT(sb + MB_OFF + 1 * 16 + nbuf * 8, 4096u);
    }

    // prefetch gate preacts for both groups (finalize lanes)
    float xv[2][4];
    if (lane < 4) {
#pragma unroll
      for (int g = 0; g < 2; g++) {
        const float* xp = xg_b[g] + (size_t)t * G4_;
        xv[g][0] = xp[0];
        xv[g][1] = xp[256];
        xv[g][2] = xp[512];
        xv[g][3] = xp[768];
      }
    }

#pragma unroll
    for (int g = 0; g < 2; g++) {
      if (t > 0) WAIT_MBAR(sb + MB_OFF + g * 16 + buf * 8, wpar);

      // matmul over this lane's 32 k (pre-duplicated h, no PACK needed)
      const ulonglong2* hbp =
          (const ulonglong2*)(sm + g * HB_G_B + buf * HB_BUF_B + q * 528);
      uint64_t a0 = 0ull, a1 = 0ull;
#pragma unroll
      for (int kk = 0; kk < 32; kk++) {
        ulonglong2 hv = hbp[kk];
        FMA2(a0, wp[kk], hv.x);
        FMA2(a1, wp[kk], hv.y);
      }
      // butterfly over q (lanes stride 4)
#pragma unroll
      for (int m = 4; m <= 16; m <<= 1) {
        uint64_t o0 = __shfl_xor_sync(0xFFFFFFFFu, a0, m);
        uint64_t o1 = __shfl_xor_sync(0xFFFFFFFFu, a1, m);
        ADD2(a0, a0, o0);
        ADD2(a1, a1, o1);
      }
      if (lane < 4) {             // q==0 lanes hold gate totals
        sx[gate * 2 + 0] = a0;    // b0
        sx[gate * 2 + 1] = a1;    // b1
      }
      __syncwarp();

      if (lane < 4) {             // finalize (u, b)
        float gi = xv[g][0] + scr[(0 * 2 + b) * 2 + u];
        float gf = xv[g][1] + scr[(1 * 2 + b) * 2 + u];
        float gg = xv[g][2] + scr[(2 * 2 + b) * 2 + u];
        float go = xv[g][3] + scr[(3 * 2 + b) * 2 + u];
        float ig = fast_sigmoid(gi);
        float fg = fast_sigmoid(gf);
        float og = fast_sigmoid(go);
        float gt = fast_tanh(gg);
        float c  = fg * cst[g] + ig * gt;
        float h  = og * fast_tanh(c);
        cst[g] = c * mcv[g];
        out[out_b[g] + (size_t)t * H_] = h * mo[g];
        float hm = h * mhv[g];
        uint64_t hd;
        PACKD(hd, hm);
        sx[8 + u * 2 + b] = hd;   // hstage duplicated {hm,hm}
      }
      __syncwarp();

      {                           // broadcast: each lane one 8 B piece
        uint64_t v;
        asm volatile("ld.shared.b64 %0, [%1];" : "=l"(v) : "r"(src_hst));
        uint32_t da = r_hb[g] + (uint32_t)nbuf * HB_BUF_B;
        uint32_t db = r_mb[g] + (uint32_t)nbuf * 8;
        asm volatile(
            "st.async.shared::cluster.mbarrier::complete_tx::bytes.b64 "
            "[%0], %1, [%2];"
            :: "r"(da), "l"(v), "r"(db) : "memory");
      }
      __syncwarp();               // protect scratch before other group reuses
    }
  }

  // drain the last in-flight phase (stores of t=511 into buf 0)
  {
    uint32_t fpar = (uint32_t)(((T_ - 1) >> 1) & 1);
    WAIT_MBAR(sb + MB_OFF + 0 * 16 + 0 * 8, fpar);
    WAIT_MBAR(sb + MB_OFF + 1 * 16 + 0 * 8, fpar);
  }
  asm volatile("barrier.cluster.arrive.aligned;" ::: "memory");
  asm volatile("barrier.cluster.wait.aligned;"   ::: "memory");
}

// ---------------- launcher ---------------------------------------------------
extern "C" void kernel_launch(void* const* d_in, const int* in_sizes, int n_in,
                              void* d_out, int out_size) {
  const float* x     = (const float*)d_in[0];
  const float* W_ih0 = (const float*)d_in[1];
  const float* W_hh0 = (const float*)d_in[2];
  const float* b_ih0 = (const float*)d_in[3];
  const float* b_hh0 = (const float*)d_in[4];
  const float* W_ih1 = (const float*)d_in[5];
  const float* W_hh1 = (const float*)d_in[6];
  const float* b_ih1 = (const float*)d_in[7];
  const float* b_hh1 = (const float*)d_in[8];
  float* out = (float*)d_out;

  float *xg, *y1, *masks;
  cudaGetSymbolAddress((void**)&xg, g_xg);
  cudaGetSymbolAddress((void**)&y1, g_y1);
  cudaGetSymbolAddress((void**)&masks, g_masks);

  mask_kernel<<<dim3(64, 6), 256>>>();

  gemm_xg_kernel<<<dim3(8, 256), 256>>>(x, W_ih0, b_ih0, b_hh0, xg);
  lstm_layer_kernel<<<128, 512>>>(
      xg, W_hh0, masks + 0 * 16384, masks + 1 * 16384, masks + 2 * 16384, y1);

  gemm_xg_kernel<<<dim3(8, 256), 256>>>(y1, W_ih1, b_ih1, b_hh1, xg);
  lstm_layer_kernel<<<128, 512>>>(
      xg, W_hh1, masks + 3 * 16384, masks + 4 * 16384, masks + 5 * 16384, out);
}